// round 4
// baseline (speedup 1.0000x reference)
#include <cuda_runtime.h>
#include <cstdint>

#define BOND_CUTOFF 3.6f

// ---------------------------------------------------------------------------
// Fused single-launch kernel: thresholded L1 distance matrix on x[:, :3]
// of the stride-7 input.
//
// Round-1-identical tiling (the measured best for the store stream):
//   Block: 256 threads. Tile: TI=16 rows x TJ=1024 cols. Grid 8 x 512 = 4096.
//   Each thread owns 4 consecutive columns in registers, loops 16 rows,
//   one coalesced float4 store per row (warp covers 2KB contiguous).
//
// Row positions are staged in shared memory once per block (uniform-index
// LDS broadcast in the inner loop); column positions are read stride-7 once
// per thread (12 L2-hot scalar loads amortized over 16 rows).
// ---------------------------------------------------------------------------
#define TI 16
#define TJ 1024

__global__ __launch_bounds__(256, 8)
void graph_kernel(const float* __restrict__ x, float* __restrict__ out, int n) {
    __shared__ float s_rx[TI], s_ry[TI], s_rz[TI];

    const int t  = threadIdx.x;
    const int i0 = blockIdx.y * TI;
    const int j0 = blockIdx.x * TJ + t * 4;   // this thread's 4 columns

    // Stage the 16 row positions into shared memory.
    if (t < TI) {
        const float* pr = x + (size_t)(i0 + t) * 7;
        s_rx[t] = pr[0];
        s_ry[t] = pr[1];
        s_rz[t] = pr[2];
    }

    // One-time column position loads, straight from stride-7 input (L2-hot).
    float cx[4], cy[4], cz[4];
#pragma unroll
    for (int k = 0; k < 4; k++) {
        const float* p = x + (size_t)(j0 + k) * 7;
        cx[k] = p[0]; cy[k] = p[1]; cz[k] = p[2];
    }

    __syncthreads();

    float* orow = out + (size_t)i0 * n + j0;

#pragma unroll
    for (int r = 0; r < TI; r++) {
        // Uniform-index LDS broadcast (conflict-free).
        float px = s_rx[r], py = s_ry[r], pz = s_rz[r];

        float4 res;
        {
            float d0 = (fabsf(px - cx[0]) + fabsf(py - cy[0])) + fabsf(pz - cz[0]);
            float d1 = (fabsf(px - cx[1]) + fabsf(py - cy[1])) + fabsf(pz - cz[1]);
            float d2 = (fabsf(px - cx[2]) + fabsf(py - cy[2])) + fabsf(pz - cz[2]);
            float d3 = (fabsf(px - cx[3]) + fabsf(py - cy[3])) + fabsf(pz - cz[3]);
            res.x = (d0 <= BOND_CUTOFF) ? 1.0f : 0.0f;
            res.y = (d1 <= BOND_CUTOFF) ? 1.0f : 0.0f;
            res.z = (d2 <= BOND_CUTOFF) ? 1.0f : 0.0f;
            res.w = (d3 <= BOND_CUTOFF) ? 1.0f : 0.0f;
        }

        *reinterpret_cast<float4*>(orow) = res;
        orow += n;
    }
}

// ---------------------------------------------------------------------------
// Fallback for shapes that don't tile evenly (defensive; N=8192 does).
// ---------------------------------------------------------------------------
__global__ void graph_kernel_generic(const float* __restrict__ x,
                                     float* __restrict__ out, int n) {
    int j = blockIdx.x * blockDim.x + threadIdx.x;
    int i = blockIdx.y;
    if (i < n && j < n) {
        const float* pi = x + (size_t)i * 7;
        const float* pj = x + (size_t)j * 7;
        float d = (fabsf(pi[0] - pj[0]) + fabsf(pi[1] - pj[1])) + fabsf(pi[2] - pj[2]);
        out[(size_t)i * n + j] = (d <= BOND_CUTOFF) ? 1.0f : 0.0f;
    }
}

extern "C" void kernel_launch(void* const* d_in, const int* in_sizes, int n_in,
                              void* d_out, int out_size) {
    const float* x = (const float*)d_in[0];
    int n = in_sizes[0] / 7;
    float* out = (float*)d_out;

    if (n > 0 && (n % TJ) == 0 && (n % TI) == 0) {
        dim3 grid(n / TJ, n / TI);
        graph_kernel<<<grid, 256>>>(x, out, n);
    } else {
        dim3 grid((n + 255) / 256, n);
        graph_kernel_generic<<<grid, 256>>>(x, out, n);
    }
}

// round 5
// speedup vs baseline: 1.1570x; 1.1570x over previous
#include <cuda_runtime.h>
#include <cstdint>

#define BOND_CUTOFF 3.6f
#define N_MAX 8192

// Static scratch: packed positions (x,y,z,pad). 8192 * 16 B = 128 KB.
__device__ float4 g_pos[N_MAX];

// ---------------------------------------------------------------------------
// Kernel 1: pack stride-7 input into contiguous float4 array.
// ---------------------------------------------------------------------------
__global__ void pack_pos_kernel(const float* __restrict__ x, int n) {
    int j = blockIdx.x * blockDim.x + threadIdx.x;
    if (j < n) {
        const float* p = x + (size_t)j * 7;
        g_pos[j] = make_float4(p[0], p[1], p[2], 0.0f);
    }
}

// ---------------------------------------------------------------------------
// Kernel 2: thresholded L1 distance matrix (round-1 structure, TI=8).
// Block: 256 threads. Tile: TI=8 rows x TJ=1024 cols. Grid 8 x 1024 = 8192.
// Each thread owns 4 consecutive columns (coalesced float4 loads from the
// packed array), loops 8 rows, one coalesced float4 store per row.
// Smaller T_CTA than round 1 -> finer wave granularity, smaller tail.
// ---------------------------------------------------------------------------
#define TI 8
#define TJ 1024

__global__ __launch_bounds__(256, 8)
void graph_kernel(float* __restrict__ out, int n) {
    const int t  = threadIdx.x;
    const int j0 = blockIdx.x * TJ + t * 4;   // first of this thread's 4 cols
    const int i0 = blockIdx.y * TI;

    // Coalesced packed loads: lanes at 16B stride -> 4 wavefronts per LDG.128.
    float4 c0 = g_pos[j0 + 0];
    float4 c1 = g_pos[j0 + 1];
    float4 c2 = g_pos[j0 + 2];
    float4 c3 = g_pos[j0 + 3];

    float* orow = out + (size_t)i0 * n + j0;

#pragma unroll
    for (int r = 0; r < TI; r++) {
        // Uniform broadcast load (1 wavefront, L1 hit).
        float4 pi = g_pos[i0 + r];

        float4 res;
        {
            float d0 = (fabsf(pi.x - c0.x) + fabsf(pi.y - c0.y)) + fabsf(pi.z - c0.z);
            float d1 = (fabsf(pi.x - c1.x) + fabsf(pi.y - c1.y)) + fabsf(pi.z - c1.z);
            float d2 = (fabsf(pi.x - c2.x) + fabsf(pi.y - c2.y)) + fabsf(pi.z - c2.z);
            float d3 = (fabsf(pi.x - c3.x) + fabsf(pi.y - c3.y)) + fabsf(pi.z - c3.z);
            res.x = (d0 <= BOND_CUTOFF) ? 1.0f : 0.0f;
            res.y = (d1 <= BOND_CUTOFF) ? 1.0f : 0.0f;
            res.z = (d2 <= BOND_CUTOFF) ? 1.0f : 0.0f;
            res.w = (d3 <= BOND_CUTOFF) ? 1.0f : 0.0f;
        }

        *reinterpret_cast<float4*>(orow) = res;
        orow += n;
    }
}

// ---------------------------------------------------------------------------
// Fallback for shapes that don't tile evenly (defensive; N=8192 does).
// ---------------------------------------------------------------------------
__global__ void graph_kernel_generic(float* __restrict__ out, int n) {
    int j = blockIdx.x * blockDim.x + threadIdx.x;
    int i = blockIdx.y;
    if (i < n && j < n) {
        float4 pi = g_pos[i];
        float4 pj = g_pos[j];
        float d = (fabsf(pi.x - pj.x) + fabsf(pi.y - pj.y)) + fabsf(pi.z - pj.z);
        out[(size_t)i * n + j] = (d <= BOND_CUTOFF) ? 1.0f : 0.0f;
    }
}

extern "C" void kernel_launch(void* const* d_in, const int* in_sizes, int n_in,
                              void* d_out, int out_size) {
    const float* x = (const float*)d_in[0];
    int n = in_sizes[0] / 7;
    float* out = (float*)d_out;

    pack_pos_kernel<<<(n + 255) / 256, 256>>>(x, n);

    if (n > 0 && n <= N_MAX && (n % TJ) == 0 && (n % TI) == 0) {
        dim3 grid(n / TJ, n / TI);
        graph_kernel<<<grid, 256>>>(out, n);
    } else {
        dim3 grid((n + 255) / 256, n);
        graph_kernel_generic<<<grid, 256>>>(out, n);
    }
}